// round 13
// baseline (speedup 1.0000x reference)
#include <cuda_runtime.h>
#include <math.h>
#include <stdint.h>

#define Bsz   64
#define Tlen  256
#define Din   128
#define Hd    1024
#define Ld    5
#define Cd    10
#define FourH 4096
#define Mrows (Tlen * Bsz)   // 16384
#define BHd   (Bsz * Hd)

// ---------------- scratch (static device globals; no allocs) ----------------
// xproj layout is GATE-INTERLEAVED: xproj[row][hcol][gate], gate order i,f,g,o
__device__ float g_xproj[(size_t)Mrows * FourH];   // 256 MB
__device__ float g_hseq0[(size_t)Mrows * Hd];      // 64 MB (tf32-prerounded)
__device__ float g_hseq1[(size_t)Mrows * Hd];      // 64 MB (tf32-prerounded)
__device__ float g_hfull[BHd];                     // full precision final h (head)
__device__ float g_hr0[BHd];                       // tf32-prerounded (last layer only)
__device__ float g_hr1[BHd];
__device__ float g_xtf[(size_t)Bsz * Tlen * Din];          // prerounded x
__device__ float g_wtf[(size_t)(Din + 4 * Hd) * FourH];    // prerounded TRANSPOSED Wx0|Wxs
__device__ unsigned g_sync[128 * 32];   // per-block epoch flags (128B strided)

// ---------------- PTX helpers ----------------
__device__ __forceinline__ uint32_t f2tf32(float f) {
    uint32_t u; asm("cvt.rna.tf32.f32 %0, %1;" : "=r"(u) : "f"(f)); return u;
}
__device__ __forceinline__ void ldsm_x4(uint32_t& r0, uint32_t& r1, uint32_t& r2,
                                        uint32_t& r3, uint32_t addr) {
    asm volatile("ldmatrix.sync.aligned.m8n8.x4.shared.b16 {%0,%1,%2,%3}, [%4];"
                 : "=r"(r0), "=r"(r1), "=r"(r2), "=r"(r3) : "r"(addr));
}
__device__ __forceinline__ void mma_tf32(float* d, uint32_t a0, uint32_t a1,
                                         uint32_t a2, uint32_t a3,
                                         uint32_t b0, uint32_t b1) {
    asm volatile("mma.sync.aligned.m16n8k8.row.col.f32.tf32.tf32.f32 "
                 "{%0,%1,%2,%3}, {%4,%5,%6,%7}, {%8,%9}, {%0,%1,%2,%3};"
                 : "+f"(d[0]), "+f"(d[1]), "+f"(d[2]), "+f"(d[3])
                 : "r"(a0), "r"(a1), "r"(a2), "r"(a3), "r"(b0), "r"(b1));
}
__device__ __forceinline__ void cp16(uint32_t dst, const void* src) {
    asm volatile("cp.async.cg.shared.global [%0], [%1], 16;" :: "r"(dst), "l"(src));
}
__device__ __forceinline__ void cp_commit() {
    asm volatile("cp.async.commit_group;");
}
template <int N>
__device__ __forceinline__ void cp_wait() {
    asm volatile("cp.async.wait_group %0;" :: "n"(N));
}

// ---------------- grid barrier: all-to-all flag scan ----------------
__device__ __forceinline__ void grid_sync(unsigned epoch) {
    __syncthreads();
    if (threadIdx.x == 0) {
        __threadfence();
        asm volatile("st.release.gpu.global.u32 [%0], %1;"
                     :: "l"(&g_sync[blockIdx.x * 32]), "r"(epoch) : "memory");
    }
    if (threadIdx.x < 128) {
        unsigned v;
        do {
            asm volatile("ld.acquire.gpu.global.u32 %0, [%1];"
                         : "=r"(v) : "l"(&g_sync[threadIdx.x * 32]) : "memory");
        } while (v < epoch);
    }
    __syncthreads();
}

// ---------------- fast activations ----------------
__device__ __forceinline__ float sigmoid_f(float x) {
    return __fdividef(1.f, 1.f + __expf(-x));
}
__device__ __forceinline__ float tanh_f(float x) {
    float e = __expf(2.f * x);
    return 1.f - __fdividef(2.f, e + 1.f);
}

// ---------------- prep kernels ----------------
__global__ void preround_x(const float* __restrict__ x) {
    size_t nx = (size_t)Bsz * Tlen * Din;
    size_t stride = (size_t)gridDim.x * blockDim.x;
    for (size_t i = (size_t)blockIdx.x * blockDim.x + threadIdx.x; i < nx; i += stride)
        g_xtf[i] = __uint_as_float(f2tf32(x[i]));
}

__global__ void transpose_wx0(const float* __restrict__ src) {
    __shared__ float tile[32][33];
    int kb = blockIdx.y * 32, nb = blockIdx.x * 32;
    int tx = threadIdx.x, ty = threadIdx.y;
    for (int i = ty; i < 32; i += 8)
        tile[i][tx] = src[(size_t)(kb + i) * FourH + nb + tx];
    __syncthreads();
    for (int i = ty; i < 32; i += 8)
        g_wtf[(size_t)(nb + i) * Din + kb + tx] = __uint_as_float(f2tf32(tile[tx][i]));
}

__global__ void transpose_wxs(const float* __restrict__ src) {
    __shared__ float tile[32][33];
    int kg = blockIdx.y * 32;            // spans 4 matrices x 1024 k
    int mat = kg >> 10;
    int kb  = kg & 1023;
    int nb  = blockIdx.x * 32;
    const float* s = src + (size_t)mat * Hd * FourH;
    float* d = g_wtf + (size_t)Din * FourH + (size_t)mat * Hd * FourH;
    int tx = threadIdx.x, ty = threadIdx.y;
    for (int i = ty; i < 32; i += 8)
        tile[i][tx] = s[(size_t)(kb + i) * FourH + nb + tx];
    __syncthreads();
    for (int i = ty; i < 32; i += 8)
        d[(size_t)(nb + i) * Hd + kb + tx] = __uint_as_float(f2tf32(tile[tx][i]));
}

__global__ void reset_flags() {
    g_sync[threadIdx.x * 32] = 0u;       // 128 threads
}

// ============================================================================
// Input projection GEMM (tf32, cp.async 3-stage pipeline, ldmatrix A and B)
//   Block tile 128(M) x 256(N), k-tile 32, 512 threads = 16 warps (2m x 8n).
//   W is pre-transposed n-major: Wt[n][k].
// ============================================================================
#define PBP 36
#define STG_F (128 * 32 + 256 * PBP)       // 13312 floats per stage
#define PROJ_SMEM (3 * STG_F * 4)          // 159744 B

__global__ __launch_bounds__(512) void proj_gemm_tc(
    const float* __restrict__ A, int stride_t, int stride_b, int K,
    const float* __restrict__ Wt, const float* __restrict__ bias)
{
    extern __shared__ float ps[];
    uint32_t sbase = (uint32_t)__cvta_generic_to_shared(ps);

    int tid  = threadIdx.x;
    int wid  = tid >> 5;
    int lane = tid & 31;
    int row0 = blockIdx.y * 128;
    int col0 = blockIdx.x * 256;

    int wm = wid & 1;          // m-group (64 rows)
    int wn = wid >> 1;         // n-group (32 cols)

    // A issue mapping
    int a_row = tid >> 2;
    int a_c2  = (tid & 3) * 2;
    int agrow = row0 + a_row;
    const float* Aptr = A + (size_t)(agrow >> 6) * stride_t
                          + (size_t)(agrow & 63) * stride_b;
    int a_sw0 = a_row * 32 + ((a_c2)     ^ (a_row & 7)) * 4;
    int a_sw1 = a_row * 32 + ((a_c2 + 1) ^ (a_row & 7)) * 4;

    // ldmatrix lane components (A)
    int lm_row = (lane & 7) + ((lane >> 3) & 1) * 8;
    int lm_cs  = lane >> 4;
    int lm_x   = lane & 7;

    // ldmatrix lane components (B): matrix idx m = lane>>3
    int b_m   = lane >> 3;          // 0..3
    int b_nt4 = b_m >> 1;           // sub n-tile within pair
    int b_kc  = b_m & 1;            // k chunk (0 or +4)
    int b_r   = lane & 7;           // row within 8

    float acc[4][4][4];
#pragma unroll
    for (int i = 0; i < 4; i++)
#pragma unroll
        for (int j = 0; j < 4; j++)
#pragma unroll
            for (int r = 0; r < 4; r++) acc[i][j][r] = 0.f;

    int ntiles = K >> 5;

    auto issue = [&](int stage, int kt) {
        if (kt < ntiles) {
            int kb = kt * 32;
            uint32_t as = sbase + (stage * STG_F) * 4;
            cp16(as + a_sw0 * 4, Aptr + kb + a_c2 * 4);
            cp16(as + a_sw1 * 4, Aptr + kb + (a_c2 + 1) * 4);
            uint32_t bsm = sbase + (stage * STG_F + 128 * 32) * 4;
#pragma unroll
            for (int i = 0; i < 4; i++) {
                int id = i * 512 + tid;
                int n = id >> 3, k4 = (id & 7) * 4;
                cp16(bsm + (n * PBP + k4) * 4,
                     Wt + (size_t)(col0 + n) * K + kb + k4);
            }
        }
        cp_commit();
    };

    issue(0, 0);
    issue(1, 1);

    for (int kt = 0; kt < ntiles; kt++) {
        cp_wait<1>();
        __syncthreads();
        int cur = kt % 3;
        issue((kt + 2) % 3, kt + 2);

        uint32_t asb = sbase + (cur * STG_F) * 4;
        uint32_t bsb = sbase + (cur * STG_F + 128 * 32) * 4;

#pragma unroll
        for (int kk = 0; kk < 4; kk++) {
            uint32_t bf[4][2];
#pragma unroll
            for (int np = 0; np < 2; np++) {
                int nrow = wn * 32 + (np * 2 + b_nt4) * 8 + b_r;
                uint32_t addr = bsb + (nrow * PBP + kk * 8 + b_kc * 4) * 4;
                ldsm_x4(bf[np * 2][0], bf[np * 2][1],
                        bf[np * 2 + 1][0], bf[np * 2 + 1][1], addr);
            }
#pragma unroll
            for (int mt = 0; mt < 4; mt++) {
                int arow = wm * 64 + mt * 16 + lm_row;
                int phys = (kk * 2 + lm_cs) ^ lm_x;
                uint32_t a0, a1, a2, a3;
                ldsm_x4(a0, a1, a2, a3, asb + (arow * 32 + phys * 4) * 4);
#pragma unroll
                for (int nt = 0; nt < 4; nt++)
                    mma_tf32(acc[mt][nt], a0, a1, a2, a3, bf[nt][0], bf[nt][1]);
            }
        }
    }

    // epilogue: add bias, store gate-interleaved
    int gate  = col0 >> 10;
    int hbase = col0 & 1023;
#pragma unroll
    for (int mt = 0; mt < 4; mt++) {
        int row = row0 + wm * 64 + mt * 16 + (lane >> 2);
#pragma unroll
        for (int nt = 0; nt < 4; nt++) {
            int nl = wn * 32 + nt * 8 + 2 * (lane & 3);
            float b0v = bias[col0 + nl];
            float b1v = bias[col0 + nl + 1];
            int hcol = hbase + nl;
            float* o0 = g_xproj + (size_t)row * FourH + hcol * 4 + gate;
            o0[0] = acc[mt][nt][0] + b0v;
            o0[4] = acc[mt][nt][1] + b1v;
            float* o1 = o0 + (size_t)8 * FourH;
            o1[0] = acc[mt][nt][2] + b0v;
            o1[4] = acc[mt][nt][3] + b1v;
        }
    }
}

// ============================================================================
// Persistent recurrent layer (R11 mainloop; store/load chain stripped)
//   128 blocks x 512 threads; 16 warps = (gate g = wid&3) x (k-split s = wid>>2)
//   - layers 0..3 (writeseq): h^t read from seq + (t-1)*BHd; only seq written
//   - layer 4: hr ping-pong; g_hfull written at t=255 only
//   - c in register; t=0 fast path (no staging/mma); no state zeroing
// ============================================================================
#define RPITCH 36
#define RSEG   (64 * RPITCH)            // 2304 floats per k-split segment
#define KTF    (4 * RSEG)               // 9216 floats per staged k-tile
#define NSTG   4
#define REC_SMEM ((NSTG * KTF + 4 * RSEG) * 4)   // 184320 B

__global__ __launch_bounds__(512) void lstm_layer_tc(
    const float* __restrict__ Wh, int seqsel, int writeseq)
{
    extern __shared__ float rs[];
    float* pD = rs + NSTG * KTF;
    uint32_t sbase = (uint32_t)__cvta_generic_to_shared(rs);

    int tid  = threadIdx.x;
    int wid  = tid >> 5;
    int lane = tid & 31;
    int g    = wid & 3;
    int s    = wid >> 2;
    int c0   = blockIdx.x * 8;

    uint32_t b0[32], b1[32];
    {
        const float* Wb = Wh + (size_t)(s * 256) * FourH + g * Hd + c0 + (lane >> 2);
#pragma unroll
        for (int j = 0; j < 32; j++) {
            int k = j * 8 + (lane & 3);
            b0[j] = f2tf32(Wb[(size_t)k * FourH]);
            b1[j] = f2tf32(Wb[(size_t)(k + 4) * FourH]);
        }
    }

    float* seq = seqsel ? g_hseq1 : g_hseq0;

    int srow = wid * 4 + (lane >> 3);
    int sk4  = (lane & 7) * 4;
    int lm_row = (lane & 7) + ((lane >> 3) & 1) * 8;
    int lm_k   = (lane >> 4) * 4;
    int gm = tid >> 3, ghc = tid & 7;
    int ghi = gm * Hd + c0 + ghc;

    float creg = 0.f;           // cell state in register (static thread<->elem map)
    unsigned epoch = 0;

    for (int t = 0; t < Tlen; t++) {
        // prefetch gate-phase input
        float4 xp = *(const float4*)&g_xproj[((size_t)(t * Bsz + gm)) * FourH
                                             + (c0 + ghc) * 4];

        float acc[4][4];
#pragma unroll
        for (int mt = 0; mt < 4; mt++)
#pragma unroll
            for (int r = 0; r < 4; r++) acc[mt][r] = 0.f;

        if (t > 0) {
            // h^t: from seq (layers 0..3) or hr ping-pong (last layer)
            const float* hr_in = writeseq ? (seq + (size_t)(t - 1) * BHd)
                                          : ((t & 1) ? g_hr1 : g_hr0);
            const float* hsrc = hr_in + srow * Hd + sk4;

#pragma unroll
            for (int p = 0; p < 3; p++) {
                uint32_t dst = sbase + ((p % NSTG) * KTF + srow * RPITCH + sk4) * 4;
#pragma unroll
                for (int sp = 0; sp < 4; sp++)
                    cp16(dst + sp * RSEG * 4, hsrc + sp * 256 + p * 32);
                cp_commit();
            }

#pragma unroll
            for (int kt = 0; kt < 8; kt++) {
                cp_wait<2>();
                __syncthreads();
                if (kt + 3 < 8) {
                    uint32_t dst = sbase + (((kt + 3) % NSTG) * KTF
                                            + srow * RPITCH + sk4) * 4;
#pragma unroll
                    for (int sp = 0; sp < 4; sp++)
                        cp16(dst + sp * RSEG * 4, hsrc + sp * 256 + (kt + 3) * 32);
                }
                cp_commit();

                uint32_t asb = sbase + ((kt % NSTG) * KTF) * 4;
#pragma unroll
                for (int kk = 0; kk < 4; kk++) {
                    int j = kt * 4 + kk;
                    uint32_t addr = asb +
                        (s * RSEG + lm_row * RPITCH + kk * 8 + lm_k) * 4;
#pragma unroll
                    for (int mt = 0; mt < 4; mt++) {
                        uint32_t a0, a1, a2, a3;
                        ldsm_x4(a0, a1, a2, a3, addr + (mt * 16 * RPITCH) * 4);
                        mma_tf32(acc[mt], a0, a1, a2, a3, b0[j], b1[j]);
                    }
                }
            }
            __syncthreads();   // all reads of pD region (slot overlap-free) done
        }

        // write k-split partials (per-warp private region)
#pragma unroll
        for (int mt = 0; mt < 4; mt++) {
            int row = mt * 16 + (lane >> 2);
            float* p = pD + s * RSEG + row * RPITCH + g * 8 + 2 * (lane & 3);
            p[0] = acc[mt][0];
            p[1] = acc[mt][1];
            p[8 * RPITCH]     = acc[mt][2];
            p[8 * RPITCH + 1] = acc[mt][3];
        }
        __syncthreads();

        // fused gate phase
        {
            float zi = xp.x, zf = xp.y, zg = xp.z, zo = xp.w;
#pragma unroll
            for (int sp = 0; sp < 4; sp++) {
                const float* q = pD + sp * RSEG + gm * RPITCH;
                zi += q[ghc];
                zf += q[8 + ghc];
                zg += q[16 + ghc];
                zo += q[24 + ghc];
            }
            float si = sigmoid_f(zi);
            float sf = sigmoid_f(zf);
            float so = sigmoid_f(zo);
            float tg = tanh_f(zg);
            float cn = sf * creg + si * tg;
            float hn = so * tanh_f(cn);
            creg = cn;
            float hrnd = __uint_as_float(f2tf32(hn));
            if (writeseq) {
                seq[((size_t)(t * Bsz + gm)) * Hd + c0 + ghc] = hrnd;
            } else {
                float* hr_out = (t & 1) ? g_hr0 : g_hr1;
                hr_out[ghi] = hrnd;
                if (t == Tlen - 1) g_hfull[ghi] = hn;
            }
        }
        grid_sync(++epoch);
    }
}

// ---------------- head ----------------
__global__ void head_kernel(const float* __restrict__ Wc, const float* __restrict__ bc,
                            float* __restrict__ out)
{
    int b = blockIdx.x;
    int w = threadIdx.x >> 5;
    int lane = threadIdx.x & 31;
    const float* h = g_hfull + b * Hd;
    float s = 0.f;
    for (int k = lane; k < Hd; k += 32) s += h[k] * Wc[k * Cd + w];
#pragma unroll
    for (int o = 16; o > 0; o >>= 1) s += __shfl_down_sync(0xffffffffu, s, o);
    if (lane == 0) out[b * Cd + w] = s + bc[w];
}

// ---------------- launch ----------------
extern "C" void kernel_launch(void* const* d_in, const int* in_sizes, int n_in,
                              void* d_out, int out_size)
{
    const float* x    = (const float*)d_in[0];
    const float* Wx0  = (const float*)d_in[1];
    const float* Wxs  = (const float*)d_in[2];
    const float* Whs  = (const float*)d_in[3];
    const float* bs   = (const float*)d_in[4];
    const float* Wc   = (const float*)d_in[5];
    const float* bc   = (const float*)d_in[6];
    float* out = (float*)d_out;

    cudaFuncSetAttribute(proj_gemm_tc,
                         cudaFuncAttributeMaxDynamicSharedMemorySize, PROJ_SMEM);
    cudaFuncSetAttribute(lstm_layer_tc,
                         cudaFuncAttributeMaxDynamicSharedMemorySize, REC_SMEM);

    float* xtf = nullptr; float* wtf = nullptr;
    { void* p; cudaGetSymbolAddress(&p, g_xtf); xtf = (float*)p; }
    { void* p; cudaGetSymbolAddress(&p, g_wtf); wtf = (float*)p; }
    float* hs0 = nullptr; float* hs1 = nullptr;
    { void* p; cudaGetSymbolAddress(&p, g_hseq0); hs0 = (float*)p; }
    { void* p; cudaGetSymbolAddress(&p, g_hseq1); hs1 = (float*)p; }

    // prep: exactly 3 launches so ncu (-s 5 -c 1) lands on rec of layer 0
    preround_x<<<512, 256>>>(x);
    transpose_wx0<<<dim3(FourH / 32, Din / 32), dim3(32, 8)>>>(Wx0);
    transpose_wxs<<<dim3(FourH / 32, 4 * Hd / 32), dim3(32, 8)>>>(Wxs);

    dim3 pgrid(FourH / 256, Mrows / 128);   // 16 x 128

    for (int l = 0; l < Ld; l++) {
        const float* A  = (l == 0) ? xtf : (((l - 1) & 1) == 0 ? hs0 : hs1);
        const float* Wt = (l == 0) ? wtf : (wtf + (size_t)Din * FourH
                                               + (size_t)(l - 1) * Hd * FourH);
        int K  = (l == 0) ? Din : Hd;
        int st = (l == 0) ? Din : Bsz * Hd;
        int sb = (l == 0) ? Tlen * Din : Hd;

        proj_gemm_tc<<<pgrid, 512, PROJ_SMEM>>>(A, st, sb, K, Wt,
                                                bs + (size_t)l * FourH);

        reset_flags<<<1, 128>>>();

        const float* Wh = Whs + (size_t)l * Hd * FourH;
        lstm_layer_tc<<<128, 512, REC_SMEM>>>(Wh, l & 1, (l < Ld - 1) ? 1 : 0);
    }

    head_kernel<<<Bsz, 320>>>(Wc, bc, out);
}

// round 14
// speedup vs baseline: 1.2414x; 1.2414x over previous
#include <cuda_runtime.h>
#include <cuda_fp16.h>
#include <math.h>
#include <stdint.h>

#define Bsz   64
#define Tlen  256
#define Din   128
#define Hd    1024
#define Ld    5
#define Cd    10
#define FourH 4096
#define Mrows (Tlen * Bsz)   // 16384
#define BHd   (Bsz * Hd)

// ---------------- scratch (static device globals; no allocs) ----------------
// xproj layout is GATE-INTERLEAVED: xproj[row][hcol][gate], gate order i,f,g,o
__device__ float  g_xproj[(size_t)Mrows * FourH];   // 256 MB (fp32 accumulators)
__device__ __half g_hseq0[(size_t)Mrows * Hd];      // 32 MB (fp16 h sequence)
__device__ __half g_hseq1[(size_t)Mrows * Hd];      // 32 MB
__device__ float  g_hfull[BHd];                     // full precision final h (head)
__device__ __half g_hr0[BHd];                       // fp16 h ping-pong (last layer)
__device__ __half g_hr1[BHd];
__device__ __half g_xh[(size_t)Bsz * Tlen * Din];           // fp16 x
__device__ __half g_wtf[(size_t)(Din + 4 * Hd) * FourH];    // fp16 TRANSPOSED Wx0|Wxs
__device__ unsigned g_sync[128 * 32];   // per-block epoch flags (128B strided)

// ---------------- PTX helpers ----------------
__device__ __forceinline__ uint32_t packh2(float lo, float hi) {
    __half2 h = __floats2half2_rn(lo, hi);
    return *reinterpret_cast<uint32_t*>(&h);
}
__device__ __forceinline__ void ldsm_x4(uint32_t& r0, uint32_t& r1, uint32_t& r2,
                                        uint32_t& r3, uint32_t addr) {
    asm volatile("ldmatrix.sync.aligned.m8n8.x4.shared.b16 {%0,%1,%2,%3}, [%4];"
                 : "=r"(r0), "=r"(r1), "=r"(r2), "=r"(r3) : "r"(addr));
}
__device__ __forceinline__ void mma_f16(float* d, uint32_t a0, uint32_t a1,
                                        uint32_t a2, uint32_t a3,
                                        uint32_t b0, uint32_t b1) {
    asm volatile("mma.sync.aligned.m16n8k16.row.col.f32.f16.f16.f32 "
                 "{%0,%1,%2,%3}, {%4,%5,%6,%7}, {%8,%9}, {%0,%1,%2,%3};"
                 : "+f"(d[0]), "+f"(d[1]), "+f"(d[2]), "+f"(d[3])
                 : "r"(a0), "r"(a1), "r"(a2), "r"(a3), "r"(b0), "r"(b1));
}
__device__ __forceinline__ void cp16(uint32_t dst, const void* src) {
    asm volatile("cp.async.cg.shared.global [%0], [%1], 16;" :: "r"(dst), "l"(src));
}
__device__ __forceinline__ void cp_commit() {
    asm volatile("cp.async.commit_group;");
}
template <int N>
__device__ __forceinline__ void cp_wait() {
    asm volatile("cp.async.wait_group %0;" :: "n"(N));
}

// ---------------- grid barrier: all-to-all flag scan ----------------
__device__ __forceinline__ void grid_sync(unsigned epoch) {
    __syncthreads();
    if (threadIdx.x == 0) {
        __threadfence();
        asm volatile("st.release.gpu.global.u32 [%0], %1;"
                     :: "l"(&g_sync[blockIdx.x * 32]), "r"(epoch) : "memory");
    }
    if (threadIdx.x < 128) {
        unsigned v;
        do {
            asm volatile("ld.acquire.gpu.global.u32 %0, [%1];"
                         : "=r"(v) : "l"(&g_sync[threadIdx.x * 32]) : "memory");
        } while (v < epoch);
    }
    __syncthreads();
}

// ---------------- fast activations ----------------
__device__ __forceinline__ float sigmoid_f(float x) {
    return __fdividef(1.f, 1.f + __expf(-x));
}
__device__ __forceinline__ float tanh_f(float x) {
    float e = __expf(2.f * x);
    return 1.f - __fdividef(2.f, e + 1.f);
}

// ---------------- prep kernels ----------------
__global__ void preround_x(const float* __restrict__ x) {
    size_t nx = (size_t)Bsz * Tlen * Din;
    size_t stride = (size_t)gridDim.x * blockDim.x;
    for (size_t i = (size_t)blockIdx.x * blockDim.x + threadIdx.x; i < nx; i += stride)
        g_xh[i] = __float2half_rn(x[i]);
}

__global__ void transpose_wx0(const float* __restrict__ src) {
    __shared__ float tile[32][33];
    int kb = blockIdx.y * 32, nb = blockIdx.x * 32;
    int tx = threadIdx.x, ty = threadIdx.y;
    for (int i = ty; i < 32; i += 8)
        tile[i][tx] = src[(size_t)(kb + i) * FourH + nb + tx];
    __syncthreads();
    for (int i = ty; i < 32; i += 8)
        g_wtf[(size_t)(nb + i) * Din + kb + tx] = __float2half_rn(tile[tx][i]);
}

__global__ void transpose_wxs(const float* __restrict__ src) {
    __shared__ float tile[32][33];
    int kg = blockIdx.y * 32;            // spans 4 matrices x 1024 k
    int mat = kg >> 10;
    int kb  = kg & 1023;
    int nb  = blockIdx.x * 32;
    const float* s = src + (size_t)mat * Hd * FourH;
    __half* d = g_wtf + (size_t)Din * FourH + (size_t)mat * Hd * FourH;
    int tx = threadIdx.x, ty = threadIdx.y;
    for (int i = ty; i < 32; i += 8)
        tile[i][tx] = s[(size_t)(kb + i) * FourH + nb + tx];
    __syncthreads();
    for (int i = ty; i < 32; i += 8)
        d[(size_t)(nb + i) * Hd + kb + tx] = __float2half_rn(tile[tx][i]);
}

__global__ void reset_flags() {
    g_sync[threadIdx.x * 32] = 0u;       // 128 threads
}

// ============================================================================
// Input projection GEMM (fp16 mma m16n8k16, cp.async 3-stage pipeline)
//   Block tile 128(M) x 256(N), k-tile 32 halves, 512 threads = 16 warps (2m x 8n).
//   W pre-transposed n-major fp16: Wt[n][k]. A: fp16 [row][k].
//   Staged pitch 40 halves (80 B) -> conflict-free ldmatrix phases.
// ============================================================================
#define PPITCH 40
#define PSLOT_A (128 * PPITCH * 2)         // 10240 B
#define PSLOT_B (256 * PPITCH * 2)         // 20480 B
#define PSLOT   (PSLOT_A + PSLOT_B)        // 30720 B
#define PROJ_SMEM (3 * PSLOT)              // 92160 B

__global__ __launch_bounds__(512) void proj_gemm_tc(
    const __half* __restrict__ A, int stride_t, int stride_b, int K,
    const __half* __restrict__ Wt, const float* __restrict__ bias)
{
    extern __shared__ char psb[];
    uint32_t sbase = (uint32_t)__cvta_generic_to_shared(psb);

    int tid  = threadIdx.x;
    int wid  = tid >> 5;
    int lane = tid & 31;
    int row0 = blockIdx.y * 128;
    int col0 = blockIdx.x * 256;

    int wm = wid & 1;          // m-group (64 rows)
    int wn = wid >> 1;         // n-group (32 cols)

    // A staging map: row = tid>>2, 8-half seg = tid&3
    int a_row = tid >> 2;
    int a_seg = tid & 3;
    int agrow = row0 + a_row;
    const __half* Aptr = A + (size_t)(agrow >> 6) * stride_t
                           + (size_t)(agrow & 63) * stride_b;

    // ldmatrix lane address components (shared by A and B patterns)
    int l_r8 = lane & 7;
    int l_m1 = (lane >> 3) & 1;
    int l_m2 = lane >> 4;

    float acc[4][4][4];
#pragma unroll
    for (int i = 0; i < 4; i++)
#pragma unroll
        for (int j = 0; j < 4; j++)
#pragma unroll
            for (int r = 0; r < 4; r++) acc[i][j][r] = 0.f;

    int ntiles = K >> 5;

    auto issue = [&](int stage, int kt) {
        if (kt < ntiles) {
            int kb = kt * 32;
            uint32_t sa = sbase + stage * PSLOT;
            cp16(sa + (a_row * PPITCH + a_seg * 8) * 2, Aptr + kb + a_seg * 8);
            uint32_t sb = sa + PSLOT_A;
#pragma unroll
            for (int i = 0; i < 2; i++) {
                int id = i * 512 + tid;
                int n = id >> 2, seg = id & 3;
                cp16(sb + (n * PPITCH + seg * 8) * 2,
                     Wt + (size_t)(col0 + n) * K + kb + seg * 8);
            }
        }
        cp_commit();
    };

    issue(0, 0);
    issue(1, 1);

    for (int kt = 0; kt < ntiles; kt++) {
        cp_wait<1>();
        __syncthreads();
        int cur = kt % 3;
        issue((kt + 2) % 3, kt + 2);

        uint32_t asb = sbase + cur * PSLOT;
        uint32_t bsb = asb + PSLOT_A;

#pragma unroll
        for (int kk = 0; kk < 2; kk++) {
            uint32_t bf[4][2];
#pragma unroll
            for (int ntq = 0; ntq < 2; ntq++) {
                int n_row = wn * 32 + ntq * 16 + l_r8 + l_m2 * 8;
                int k_off = kk * 16 + l_m1 * 8;
                ldsm_x4(bf[2 * ntq][0], bf[2 * ntq][1],
                        bf[2 * ntq + 1][0], bf[2 * ntq + 1][1],
                        bsb + (n_row * PPITCH + k_off) * 2);
            }
#pragma unroll
            for (int mt = 0; mt < 4; mt++) {
                int ar = wm * 64 + mt * 16 + l_r8 + l_m1 * 8;
                int ak = kk * 16 + l_m2 * 8;
                uint32_t a0, a1, a2, a3;
                ldsm_x4(a0, a1, a2, a3, asb + (ar * PPITCH + ak) * 2);
#pragma unroll
                for (int nt = 0; nt < 4; nt++)
                    mma_f16(acc[mt][nt], a0, a1, a2, a3, bf[nt][0], bf[nt][1]);
            }
        }
    }

    // epilogue: add bias, store gate-interleaved (fp32)
    int gate  = col0 >> 10;
    int hbase = col0 & 1023;
#pragma unroll
    for (int mt = 0; mt < 4; mt++) {
        int row = row0 + wm * 64 + mt * 16 + (lane >> 2);
#pragma unroll
        for (int nt = 0; nt < 4; nt++) {
            int nl = wn * 32 + nt * 8 + 2 * (lane & 3);
            float b0v = bias[col0 + nl];
            float b1v = bias[col0 + nl + 1];
            int hcol = hbase + nl;
            float* o0 = g_xproj + (size_t)row * FourH + hcol * 4 + gate;
            o0[0] = acc[mt][nt][0] + b0v;
            o0[4] = acc[mt][nt][1] + b1v;
            float* o1 = o0 + (size_t)8 * FourH;
            o1[0] = acc[mt][nt][2] + b0v;
            o1[4] = acc[mt][nt][3] + b1v;
        }
    }
}

// ============================================================================
// Persistent recurrent layer (fp16 mma m16n8k16, 4-stage cp.async ring)
//   128 blocks x 512 threads; 16 warps = (gate g = wid&3) x (k-split s = wid>>2)
//   h staged fp16: per split 64 rows x 32 halves per tile, pitch 40 halves.
//   - layers 0..3 (writeseq): h^t read from seq + (t-1)*BHd; only seq written
//   - layer 4: hr ping-pong; g_hfull (fp32) written at t=255
// ============================================================================
#define RPH     40                       // staged pitch (halves)
#define RSEG_B  (64 * RPH * 2)           // 5120 B per split per tile
#define KTF_B   (4 * RSEG_B)             // 20480 B per staged tile
#define NSTG    4
#define PDPITCH 36
#define PDSEG   (64 * PDPITCH)
#define REC_SMEM (NSTG * KTF_B + 4 * PDSEG * 4)   // 81920 + 36864 = 118784 B

__global__ __launch_bounds__(512) void lstm_layer_tc(
    const float* __restrict__ Wh, int seqsel, int writeseq)
{
    extern __shared__ char rsb[];
    float* pD = (float*)(rsb + NSTG * KTF_B);
    uint32_t sbase = (uint32_t)__cvta_generic_to_shared(rsb);

    int tid  = threadIdx.x;
    int wid  = tid >> 5;
    int lane = tid & 31;
    int g    = wid & 3;
    int s    = wid >> 2;
    int c0   = blockIdx.x * 8;

    // ---- Wh slice into registers as fp16 B-fragments (m16n8k16) ----
    uint32_t b0[16], b1[16];
    {
        const float* Wb = Wh + (size_t)(g * Hd + c0 + (lane >> 2));
#pragma unroll
        for (int j = 0; j < 16; j++) {
            int kb2 = s * 256 + j * 16 + (lane & 3) * 2;
            b0[j] = packh2(Wb[(size_t)kb2 * FourH], Wb[(size_t)(kb2 + 1) * FourH]);
            b1[j] = packh2(Wb[(size_t)(kb2 + 8) * FourH], Wb[(size_t)(kb2 + 9) * FourH]);
        }
    }

    __half* seq = seqsel ? g_hseq1 : g_hseq0;

    // staging map: srow = tid>>3; q = tid&7 -> split (q>>1), 32B part (q&1)
    int srow = tid >> 3;
    int sp   = (tid & 7) >> 1;
    int part = tid & 1;

    // ldmatrix lane components
    int l_r8 = lane & 7;
    int l_m1 = (lane >> 3) & 1;
    int l_m2 = lane >> 4;

    int gm = tid >> 3, ghc = tid & 7;
    int ghi = gm * Hd + c0 + ghc;

    float creg = 0.f;
    unsigned epoch = 0;

    for (int t = 0; t < Tlen; t++) {
        float4 xp = *(const float4*)&g_xproj[((size_t)(t * Bsz + gm)) * FourH
                                             + (c0 + ghc) * 4];

        float acc[4][4];
#pragma unroll
        for (int mt = 0; mt < 4; mt++)
#pragma unroll
            for (int r = 0; r < 4; r++) acc[mt][r] = 0.f;

        if (t > 0) {
            const __half* hr_in = writeseq ? (seq + (size_t)(t - 1) * BHd)
                                           : ((t & 1) ? g_hr1 : g_hr0);
            const __half* hsrc = hr_in + srow * Hd + sp * 256 + part * 16;
            uint32_t dbase = sbase + sp * RSEG_B + srow * (RPH * 2) + part * 32;

#pragma unroll
            for (int p = 0; p < 3; p++) {
                uint32_t dst = dbase + (p % NSTG) * KTF_B;
                cp16(dst,      hsrc + p * 32);
                cp16(dst + 16, hsrc + p * 32 + 8);
                cp_commit();
            }

#pragma unroll
            for (int kt = 0; kt < 8; kt++) {
                cp_wait<2>();
                __syncthreads();
                if (kt + 3 < 8) {
                    uint32_t dst = dbase + ((kt + 3) % NSTG) * KTF_B;
                    cp16(dst,      hsrc + (kt + 3) * 32);
                    cp16(dst + 16, hsrc + (kt + 3) * 32 + 8);
                }
                cp_commit();

                uint32_t asb = sbase + (kt % NSTG) * KTF_B + s * RSEG_B;
#pragma unroll
                for (int kk = 0; kk < 2; kk++) {
                    int j = kt * 2 + kk;
                    int ak = kk * 16 + l_m2 * 8;
#pragma unroll
                    for (int mt = 0; mt < 4; mt++) {
                        int ar = mt * 16 + l_r8 + l_m1 * 8;
                        uint32_t a0, a1, a2, a3;
                        ldsm_x4(a0, a1, a2, a3, asb + (ar * RPH + ak) * 2);
                        mma_f16(acc[mt], a0, a1, a2, a3, b0[j], b1[j]);
                    }
                }
            }
            __syncthreads();
        }

        // write k-split partials (per-warp private region)
#pragma unroll
        for (int mt = 0; mt < 4; mt++) {
            int row = mt * 16 + (lane >> 2);
            float* p = pD + s * PDSEG + row * PDPITCH + g * 8 + 2 * (lane & 3);
            p[0] = acc[mt][0];
            p[1] = acc[mt][1];
            p[8 * PDPITCH]     = acc[mt][2];
            p[8 * PDPITCH + 1] = acc[mt][3];
        }
        __syncthreads();

        // fused gate phase
        {
            float zi = xp.x, zf = xp.y, zg = xp.z, zo = xp.w;
#pragma unroll
            for (int spp = 0; spp < 4; spp++) {
                const float* q = pD + spp * PDSEG + gm * PDPITCH;
                zi += q[ghc];
                zf += q[8 + ghc];
                zg += q[16 + ghc];
                zo += q[24 + ghc];
            }
            float si = sigmoid_f(zi);
            float sf = sigmoid_f(zf);
            float so = sigmoid_f(zo);
            float tg = tanh_f(zg);
            float cn = sf * creg + si * tg;
            float hn = so * tanh_f(cn);
            creg = cn;
            __half hh = __float2half_rn(hn);
            if (writeseq) {
                seq[((size_t)(t * Bsz + gm)) * Hd + c0 + ghc] = hh;
            } else {
                __half* hr_out = (t & 1) ? g_hr0 : g_hr1;
                hr_out[ghi] = hh;
                if (t == Tlen - 1) g_hfull[ghi] = hn;
            }
        }
        grid_sync(++epoch);
    }
}

// ---------------- head ----------------
__global__ void head_kernel(const float* __restrict__ Wc, const float* __restrict__ bc,
                            float* __restrict__ out)
{
    int b = blockIdx.x;
    int w = threadIdx.x >> 5;
    int lane = threadIdx.x & 31;
    const float* h = g_hfull + b * Hd;
    float s = 0.f;
    for (int k = lane; k < Hd; k += 32) s += h[k] * Wc[k * Cd + w];
#pragma unroll
    for (int o = 16; o > 0; o >>= 1) s += __shfl_down_sync(0xffffffffu, s, o);
    if (lane == 0) out[b * Cd + w] = s + bc[w];
}

// ---------------- launch ----------------
extern "C" void kernel_launch(void* const* d_in, const int* in_sizes, int n_in,
                              void* d_out, int out_size)
{
    const float* x    = (const float*)d_in[0];
    const float* Wx0  = (const float*)d_in[1];
    const float* Wxs  = (const float*)d_in[2];
    const float* Whs  = (const float*)d_in[3];
    const float* bs   = (const float*)d_in[4];
    const float* Wc   = (const float*)d_in[5];
    const float* bc   = (const float*)d_in[6];
    float* out = (float*)d_out;

    cudaFuncSetAttribute(proj_gemm_tc,
                         cudaFuncAttributeMaxDynamicSharedMemorySize, PROJ_SMEM);
    cudaFuncSetAttribute(lstm_layer_tc,
                         cudaFuncAttributeMaxDynamicSharedMemorySize, REC_SMEM);

    __half* xh = nullptr; __half* wtf = nullptr;
    { void* p; cudaGetSymbolAddress(&p, g_xh); xh = (__half*)p; }
    { void* p; cudaGetSymbolAddress(&p, g_wtf); wtf = (__half*)p; }
    __half* hs0 = nullptr; __half* hs1 = nullptr;
    { void* p; cudaGetSymbolAddress(&p, g_hseq0); hs0 = (__half*)p; }
    { void* p; cudaGetSymbolAddress(&p, g_hseq1); hs1 = (__half*)p; }

    // prep: 3 launches
    preround_x<<<512, 256>>>(x);
    transpose_wx0<<<dim3(FourH / 32, Din / 32), dim3(32, 8)>>>(Wx0);
    transpose_wxs<<<dim3(FourH / 32, 4 * Hd / 32), dim3(32, 8)>>>(Wxs);

    dim3 pgrid(FourH / 256, Mrows / 128);   // 16 x 128

    for (int l = 0; l < Ld; l++) {
        const __half* A  = (l == 0) ? xh : (((l - 1) & 1) == 0 ? hs0 : hs1);
        const __half* Wt = (l == 0) ? wtf : (wtf + (size_t)Din * FourH
                                                + (size_t)(l - 1) * Hd * FourH);
        int K  = (l == 0) ? Din : Hd;
        int st = (l == 0) ? Din : Bsz * Hd;
        int sb = (l == 0) ? Tlen * Din : Hd;

        proj_gemm_tc<<<pgrid, 512, PROJ_SMEM>>>(A, st, sb, K, Wt,
                                                bs + (size_t)l * FourH);

        reset_flags<<<1, 128>>>();

        const float* Wh = Whs + (size_t)l * Hd * FourH;
        lstm_layer_tc<<<128, 512, REC_SMEM>>>(Wh, l & 1, (l < Ld - 1) ? 1 : 0);
    }

    head_kernel<<<Bsz, 320>>>(Wc, bc, out);
}

// round 15
// speedup vs baseline: 1.3615x; 1.0967x over previous
#include <cuda_runtime.h>
#include <cuda_fp16.h>
#include <math.h>
#include <stdint.h>

#define Bsz   64
#define Tlen  256
#define Din   128
#define Hd    1024
#define Ld    5
#define Cd    10
#define FourH 4096
#define Mrows (Tlen * Bsz)   // 16384
#define BHd   (Bsz * Hd)

// ---------------- scratch (static device globals; no allocs) ----------------
// xproj layout is GATE-INTERLEAVED: xproj[row][hcol][gate], gate order i,f,g,o
__device__ float  g_xproj[(size_t)Mrows * FourH];   // 256 MB (fp32 accumulators)
__device__ __half g_hseq0[(size_t)Mrows * Hd];      // 32 MB (fp16 h sequence)
__device__ __half g_hseq1[(size_t)Mrows * Hd];      // 32 MB
__device__ float  g_hfull[BHd];                     // full precision final h (head)
__device__ __half g_hr0[BHd];                       // fp16 h ping-pong (last layer)
__device__ __half g_hr1[BHd];
__device__ __half g_xh[(size_t)Bsz * Tlen * Din];           // fp16 x
__device__ __half g_wtf[(size_t)(Din + 4 * Hd) * FourH];    // fp16 TRANSPOSED Wx0|Wxs
__device__ unsigned g_sync[128 * 32];   // per-block epoch flags (128B strided)

// ---------------- PTX helpers ----------------
__device__ __forceinline__ uint32_t packh2(float lo, float hi) {
    __half2 h = __floats2half2_rn(lo, hi);
    return *reinterpret_cast<uint32_t*>(&h);
}
__device__ __forceinline__ void ldsm_x4(uint32_t& r0, uint32_t& r1, uint32_t& r2,
                                        uint32_t& r3, uint32_t addr) {
    asm volatile("ldmatrix.sync.aligned.m8n8.x4.shared.b16 {%0,%1,%2,%3}, [%4];"
                 : "=r"(r0), "=r"(r1), "=r"(r2), "=r"(r3) : "r"(addr));
}
__device__ __forceinline__ void mma_f16(float* d, uint32_t a0, uint32_t a1,
                                        uint32_t a2, uint32_t a3,
                                        uint32_t b0, uint32_t b1) {
    asm volatile("mma.sync.aligned.m16n8k16.row.col.f32.f16.f16.f32 "
                 "{%0,%1,%2,%3}, {%4,%5,%6,%7}, {%8,%9}, {%0,%1,%2,%3};"
                 : "+f"(d[0]), "+f"(d[1]), "+f"(d[2]), "+f"(d[3])
                 : "r"(a0), "r"(a1), "r"(a2), "r"(a3), "r"(b0), "r"(b1));
}
__device__ __forceinline__ void cp16(uint32_t dst, const void* src) {
    asm volatile("cp.async.cg.shared.global [%0], [%1], 16;" :: "r"(dst), "l"(src));
}
__device__ __forceinline__ void cp_commit() {
    asm volatile("cp.async.commit_group;");
}
template <int N>
__device__ __forceinline__ void cp_wait() {
    asm volatile("cp.async.wait_group %0;" :: "n"(N));
}
__device__ __forceinline__ void bar_sync(int id, int cnt) {
    asm volatile("bar.sync %0, %1;" :: "r"(id), "r"(cnt) : "memory");
}

// ---------------- grid barrier: all-to-all flag scan ----------------
__device__ __forceinline__ void grid_sync(unsigned epoch) {
    __syncthreads();
    if (threadIdx.x == 0) {
        __threadfence();
        asm volatile("st.release.gpu.global.u32 [%0], %1;"
                     :: "l"(&g_sync[blockIdx.x * 32]), "r"(epoch) : "memory");
    }
    if (threadIdx.x < 128) {
        unsigned v;
        do {
            asm volatile("ld.acquire.gpu.global.u32 %0, [%1];"
                         : "=r"(v) : "l"(&g_sync[threadIdx.x * 32]) : "memory");
        } while (v < epoch);
    }
    __syncthreads();
}

// ---------------- fast activations ----------------
__device__ __forceinline__ float sigmoid_f(float x) {
    return __fdividef(1.f, 1.f + __expf(-x));
}
__device__ __forceinline__ float tanh_f(float x) {
    float e = __expf(2.f * x);
    return 1.f - __fdividef(2.f, e + 1.f);
}

// ---------------- prep kernels ----------------
__global__ void preround_x(const float* __restrict__ x) {
    size_t nx = (size_t)Bsz * Tlen * Din;
    size_t stride = (size_t)gridDim.x * blockDim.x;
    for (size_t i = (size_t)blockIdx.x * blockDim.x + threadIdx.x; i < nx; i += stride)
        g_xh[i] = __float2half_rn(x[i]);
}

__global__ void transpose_wx0(const float* __restrict__ src) {
    __shared__ float tile[32][33];
    int kb = blockIdx.y * 32, nb = blockIdx.x * 32;
    int tx = threadIdx.x, ty = threadIdx.y;
    for (int i = ty; i < 32; i += 8)
        tile[i][tx] = src[(size_t)(kb + i) * FourH + nb + tx];
    __syncthreads();
    for (int i = ty; i < 32; i += 8)
        g_wtf[(size_t)(nb + i) * Din + kb + tx] = __float2half_rn(tile[tx][i]);
}

__global__ void transpose_wxs(const float* __restrict__ src) {
    __shared__ float tile[32][33];
    int kg = blockIdx.y * 32;            // spans 4 matrices x 1024 k
    int mat = kg >> 10;
    int kb  = kg & 1023;
    int nb  = blockIdx.x * 32;
    const float* s = src + (size_t)mat * Hd * FourH;
    __half* d = g_wtf + (size_t)Din * FourH + (size_t)mat * Hd * FourH;
    int tx = threadIdx.x, ty = threadIdx.y;
    for (int i = ty; i < 32; i += 8)
        tile[i][tx] = s[(size_t)(kb + i) * FourH + nb + tx];
    __syncthreads();
    for (int i = ty; i < 32; i += 8)
        d[(size_t)(nb + i) * Hd + kb + tx] = __float2half_rn(tile[tx][i]);
}

__global__ void reset_flags() {
    g_sync[threadIdx.x * 32] = 0u;       // 128 threads
}

// ============================================================================
// Input projection GEMM (fp16 mma m16n8k16, cp.async 3-stage pipeline)
//   Block tile 128(M) x 256(N), k-tile 32 halves, 512 threads = 16 warps (2m x 8n).
// ============================================================================
#define PPITCH 40
#define PSLOT_A (128 * PPITCH * 2)         // 10240 B
#define PSLOT_B (256 * PPITCH * 2)         // 20480 B
#define PSLOT   (PSLOT_A + PSLOT_B)        // 30720 B
#define PROJ_SMEM (3 * PSLOT)              // 92160 B

__global__ __launch_bounds__(512) void proj_gemm_tc(
    const __half* __restrict__ A, int stride_t, int stride_b, int K,
    const __half* __restrict__ Wt, const float* __restrict__ bias)
{
    extern __shared__ char psb[];
    uint32_t sbase = (uint32_t)__cvta_generic_to_shared(psb);

    int tid  = threadIdx.x;
    int wid  = tid >> 5;
    int lane = tid & 31;
    int row0 = blockIdx.y * 128;
    int col0 = blockIdx.x * 256;

    int wm = wid & 1;          // m-group (64 rows)
    int wn = wid >> 1;         // n-group (32 cols)

    int a_row = tid >> 2;
    int a_seg = tid & 3;
    int agrow = row0 + a_row;
    const __half* Aptr = A + (size_t)(agrow >> 6) * stride_t
                           + (size_t)(agrow & 63) * stride_b;

    int l_r8 = lane & 7;
    int l_m1 = (lane >> 3) & 1;
    int l_m2 = lane >> 4;

    float acc[4][4][4];
#pragma unroll
    for (int i = 0; i < 4; i++)
#pragma unroll
        for (int j = 0; j < 4; j++)
#pragma unroll
            for (int r = 0; r < 4; r++) acc[i][j][r] = 0.f;

    int ntiles = K >> 5;

    auto issue = [&](int stage, int kt) {
        if (kt < ntiles) {
            int kb = kt * 32;
            uint32_t sa = sbase + stage * PSLOT;
            cp16(sa + (a_row * PPITCH + a_seg * 8) * 2, Aptr + kb + a_seg * 8);
            uint32_t sb = sa + PSLOT_A;
#pragma unroll
            for (int i = 0; i < 2; i++) {
                int id = i * 512 + tid;
                int n = id >> 2, seg = id & 3;
                cp16(sb + (n * PPITCH + seg * 8) * 2,
                     Wt + (size_t)(col0 + n) * K + kb + seg * 8);
            }
        }
        cp_commit();
    };

    issue(0, 0);
    issue(1, 1);

    for (int kt = 0; kt < ntiles; kt++) {
        cp_wait<1>();
        __syncthreads();
        int cur = kt % 3;
        issue((kt + 2) % 3, kt + 2);

        uint32_t asb = sbase + cur * PSLOT;
        uint32_t bsb = asb + PSLOT_A;

#pragma unroll
        for (int kk = 0; kk < 2; kk++) {
            uint32_t bf[4][2];
#pragma unroll
            for (int ntq = 0; ntq < 2; ntq++) {
                int n_row = wn * 32 + ntq * 16 + l_r8 + l_m2 * 8;
                int k_off = kk * 16 + l_m1 * 8;
                ldsm_x4(bf[2 * ntq][0], bf[2 * ntq][1],
                        bf[2 * ntq + 1][0], bf[2 * ntq + 1][1],
                        bsb + (n_row * PPITCH + k_off) * 2);
            }
#pragma unroll
            for (int mt = 0; mt < 4; mt++) {
                int ar = wm * 64 + mt * 16 + l_r8 + l_m1 * 8;
                int ak = kk * 16 + l_m2 * 8;
                uint32_t a0, a1, a2, a3;
                ldsm_x4(a0, a1, a2, a3, asb + (ar * PPITCH + ak) * 2);
#pragma unroll
                for (int nt = 0; nt < 4; nt++)
                    mma_f16(acc[mt][nt], a0, a1, a2, a3, bf[nt][0], bf[nt][1]);
            }
        }
    }

    // epilogue: add bias, store gate-interleaved (fp32)
    int gate  = col0 >> 10;
    int hbase = col0 & 1023;
#pragma unroll
    for (int mt = 0; mt < 4; mt++) {
        int row = row0 + wm * 64 + mt * 16 + (lane >> 2);
#pragma unroll
        for (int nt = 0; nt < 4; nt++) {
            int nl = wn * 32 + nt * 8 + 2 * (lane & 3);
            float b0v = bias[col0 + nl];
            float b1v = bias[col0 + nl + 1];
            int hcol = hbase + nl;
            float* o0 = g_xproj + (size_t)row * FourH + hcol * 4 + gate;
            o0[0] = acc[mt][nt][0] + b0v;
            o0[4] = acc[mt][nt][1] + b1v;
            float* o1 = o0 + (size_t)8 * FourH;
            o1[0] = acc[mt][nt][2] + b0v;
            o1[4] = acc[mt][nt][3] + b1v;
        }
    }
}

// ============================================================================
// Persistent recurrent layer (fp16, per-warpgroup staging + named barriers)
//   128 blocks x 512 threads; 16 warps = (gate g = wid&3) x (k-split s = wid>>2)
//   Group s (tid>>7 == s) stages ONLY its k-range [s*256, s*256+256) into its
//   private ring region; kt loop syncs with bar.sync(1+s, 128).
// ============================================================================
#define RPH     40                       // staged pitch (halves)
#define RSEG_B  (64 * RPH * 2)           // 5120 B per split per tile
#define KTF_B   (4 * RSEG_B)             // 20480 B per staged tile
#define NSTG    4
#define PDPITCH 36
#define PDSEG   (64 * PDPITCH)
#define REC_SMEM (NSTG * KTF_B + 4 * PDSEG * 4)   // 118784 B

__global__ __launch_bounds__(512) void lstm_layer_tc(
    const float* __restrict__ Wh, int seqsel, int writeseq, unsigned epoch0)
{
    extern __shared__ char rsb[];
    float* pD = (float*)(rsb + NSTG * KTF_B);
    uint32_t sbase = (uint32_t)__cvta_generic_to_shared(rsb);

    int tid  = threadIdx.x;
    int wid  = tid >> 5;
    int lane = tid & 31;
    int g    = wid & 3;
    int s    = wid >> 2;       // == tid >> 7 : k-split group
    int c0   = blockIdx.x * 8;

    // ---- Wh slice into registers as fp16 B-fragments (m16n8k16) ----
    uint32_t b0[16], b1[16];
    {
        const float* Wb = Wh + (size_t)(g * Hd + c0 + (lane >> 2));
#pragma unroll
        for (int j = 0; j < 16; j++) {
            int kb2 = s * 256 + j * 16 + (lane & 3) * 2;
            b0[j] = packh2(Wb[(size_t)kb2 * FourH], Wb[(size_t)(kb2 + 1) * FourH]);
            b1[j] = packh2(Wb[(size_t)(kb2 + 8) * FourH], Wb[(size_t)(kb2 + 9) * FourH]);
        }
    }

    __half* seq = seqsel ? g_hseq1 : g_hseq0;

    // per-group staging map: 128 threads cover 64 rows x 32 halves (2 thr/row)
    int srow = (tid & 127) >> 1;
    int part = tid & 1;
    uint32_t dbase = sbase + s * RSEG_B + srow * (RPH * 2) + part * 32;

    int l_r8 = lane & 7;
    int l_m1 = (lane >> 3) & 1;
    int l_m2 = lane >> 4;

    int gm = tid >> 3, ghc = tid & 7;
    int ghi = gm * Hd + c0 + ghc;

    float creg = 0.f;
    unsigned epoch = epoch0;

    for (int t = 0; t < Tlen; t++) {
        float4 xp = *(const float4*)&g_xproj[((size_t)(t * Bsz + gm)) * FourH
                                             + (c0 + ghc) * 4];

        float acc[4][4];
#pragma unroll
        for (int mt = 0; mt < 4; mt++)
#pragma unroll
            for (int r = 0; r < 4; r++) acc[mt][r] = 0.f;

        if (t > 0) {
            const __half* hr_in = writeseq ? (seq + (size_t)(t - 1) * BHd)
                                           : ((t & 1) ? g_hr1 : g_hr0);
            const __half* hsrc = hr_in + srow * Hd + s * 256 + part * 16;

#pragma unroll
            for (int p = 0; p < 3; p++) {
                uint32_t dst = dbase + (p % NSTG) * KTF_B;
                cp16(dst,      hsrc + p * 32);
                cp16(dst + 16, hsrc + p * 32 + 8);
                cp_commit();
            }

#pragma unroll
            for (int kt = 0; kt < 8; kt++) {
                cp_wait<2>();
                bar_sync(1 + s, 128);
                if (kt + 3 < 8) {
                    uint32_t dst = dbase + ((kt + 3) % NSTG) * KTF_B;
                    cp16(dst,      hsrc + (kt + 3) * 32);
                    cp16(dst + 16, hsrc + (kt + 3) * 32 + 8);
                }
                cp_commit();

                uint32_t asb = sbase + (kt % NSTG) * KTF_B + s * RSEG_B;
#pragma unroll
                for (int kk = 0; kk < 2; kk++) {
                    int j = kt * 2 + kk;
                    int ak = kk * 16 + l_m2 * 8;
#pragma unroll
                    for (int mt = 0; mt < 4; mt++) {
                        int ar = mt * 16 + l_r8 + l_m1 * 8;
                        uint32_t a0, a1, a2, a3;
                        ldsm_x4(a0, a1, a2, a3, asb + (ar * RPH + ak) * 2);
                        mma_f16(acc[mt], a0, a1, a2, a3, b0[j], b1[j]);
                    }
                }
            }
        }

        // write k-split partials (per-warp private region)
#pragma unroll
        for (int mt = 0; mt < 4; mt++) {
            int row = mt * 16 + (lane >> 2);
            float* p = pD + s * PDSEG + row * PDPITCH + g * 8 + 2 * (lane & 3);
            p[0] = acc[mt][0];
            p[1] = acc[mt][1];
            p[8 * PDPITCH]     = acc[mt][2];
            p[8 * PDPITCH + 1] = acc[mt][3];
        }
        __syncthreads();

        // fused gate phase
        {
            float zi = xp.x, zf = xp.y, zg = xp.z, zo = xp.w;
#pragma unroll
            for (int spp = 0; spp < 4; spp++) {
                const float* q = pD + spp * PDSEG + gm * PDPITCH;
                zi += q[ghc];
                zf += q[8 + ghc];
                zg += q[16 + ghc];
                zo += q[24 + ghc];
            }
            float si = sigmoid_f(zi);
            float sf = sigmoid_f(zf);
            float so = sigmoid_f(zo);
            float tg = tanh_f(zg);
            float cn = sf * creg + si * tg;
            float hn = so * tanh_f(cn);
            creg = cn;
            __half hh = __float2half_rn(hn);
            if (writeseq) {
                seq[((size_t)(t * Bsz + gm)) * Hd + c0 + ghc] = hh;
            } else {
                __half* hr_out = (t & 1) ? g_hr0 : g_hr1;
                hr_out[ghi] = hh;
                if (t == Tlen - 1) g_hfull[ghi] = hn;
            }
        }
        grid_sync(++epoch);
    }
}

// ---------------- head ----------------
__global__ void head_kernel(const float* __restrict__ Wc, const float* __restrict__ bc,
                            float* __restrict__ out)
{
    int b = blockIdx.x;
    int w = threadIdx.x >> 5;
    int lane = threadIdx.x & 31;
    const float* h = g_hfull + b * Hd;
    float s = 0.f;
    for (int k = lane; k < Hd; k += 32) s += h[k] * Wc[k * Cd + w];
#pragma unroll
    for (int o = 16; o > 0; o >>= 1) s += __shfl_down_sync(0xffffffffu, s, o);
    if (lane == 0) out[b * Cd + w] = s + bc[w];
}

// ---------------- launch ----------------
extern "C" void kernel_launch(void* const* d_in, const int* in_sizes, int n_in,
                              void* d_out, int out_size)
{
    const float* x    = (const float*)d_in[0];
    const float* Wx0  = (const float*)d_in[1];
    const float* Wxs  = (const float*)d_in[2];
    const float* Whs  = (const float*)d_in[3];
    const float* bs   = (const float*)d_in[4];
    const float* Wc   = (const float*)d_in[5];
    const float* bc   = (const float*)d_in[6];
    float* out = (float*)d_out;

    cudaFuncSetAttribute(proj_gemm_tc,
                         cudaFuncAttributeMaxDynamicSharedMemorySize, PROJ_SMEM);
    cudaFuncSetAttribute(lstm_layer_tc,
                         cudaFuncAttributeMaxDynamicSharedMemorySize, REC_SMEM);

    __half* xh = nullptr; __half* wtf = nullptr;
    { void* p; cudaGetSymbolAddress(&p, g_xh); xh = (__half*)p; }
    { void* p; cudaGetSymbolAddress(&p, g_wtf); wtf = (__half*)p; }
    __half* hs0 = nullptr; __half* hs1 = nullptr;
    { void* p; cudaGetSymbolAddress(&p, g_hseq0); hs0 = (__half*)p; }
    { void* p; cudaGetSymbolAddress(&p, g_hseq1); hs1 = (__half*)p; }

    // prep: 4 launches -> ncu (-s 5 -c 1) lands on rec of layer 0 (launch #6)
    preround_x<<<512, 256>>>(x);
    transpose_wx0<<<dim3(FourH / 32, Din / 32), dim3(32, 8)>>>(Wx0);
    transpose_wxs<<<dim3(FourH / 32, 4 * Hd / 32), dim3(32, 8)>>>(Wxs);
    reset_flags<<<1, 128>>>();

    dim3 pgrid(FourH / 256, Mrows / 128);   // 16 x 128

    for (int l = 0; l < Ld; l++) {
        const __half* A  = (l == 0) ? xh : (((l - 1) & 1) == 0 ? hs0 : hs1);
        const __half* Wt = (l == 0) ? wtf : (wtf + (size_t)Din * FourH
                                                + (size_t)(l - 1) * Hd * FourH);
        int K  = (l == 0) ? Din : Hd;
        int st = (l == 0) ? Din : Bsz * Hd;
        int sb = (l == 0) ? Tlen * Din : Hd;

        proj_gemm_tc<<<pgrid, 512, PROJ_SMEM>>>(A, st, sb, K, Wt,
                                                bs + (size_t)l * FourH);

        const float* Wh = Whs + (size_t)l * Hd * FourH;
        lstm_layer_tc<<<128, 512, REC_SMEM>>>(Wh, l & 1, (l < Ld - 1) ? 1 : 0,
                                              (unsigned)l * Tlen);
    }

    head_kernel<<<Bsz, 320>>>(Wc, bc, out);
}